// round 16
// baseline (speedup 1.0000x reference)
#include <cuda_runtime.h>
#include <cstdint>

#define Tt 1024
#define Bb 64
#define Ii 512
#define Hh 1024
#define Gg 3072
#define Oo 256
#define NCTA 128

__device__ float g_h[(size_t)(Tt + 1) * Hh * Bb];   // [t][k][b], slot 0 = init^T
__device__ unsigned g_bar_count;

typedef unsigned long long u64;

__device__ __forceinline__ u64 pk2(float x, float y) {
    u64 r; asm("mov.b64 %0,{%1,%2};" : "=l"(r) : "f"(x), "f"(y)); return r;
}
__device__ __forceinline__ void f2(u64& d, u64 a, u64 b) {
    asm("fma.rn.f32x2 %0,%1,%2,%0;" : "+l"(d) : "l"(a), "l"(b));
}
__device__ __forceinline__ u64 add2(u64 a, u64 b) {
    u64 d; asm("add.rn.f32x2 %0,%1,%2;" : "=l"(d) : "l"(a), "l"(b)); return d;
}
__device__ __forceinline__ float2 up2(u64 a) {
    float2 f; asm("mov.b64 {%0,%1},%2;" : "=f"(f.x), "=f"(f.y) : "l"(a)); return f;
}
__device__ __forceinline__ float sigm(float x) { return 1.0f / (1.0f + __expf(-x)); }

__device__ __forceinline__ void cp16(void* smem, const void* g) {
    uint32_t s = (uint32_t)__cvta_generic_to_shared(smem);
    asm volatile("cp.async.cg.shared.global [%0], [%1], 16;" :: "r"(s), "l"(g));
}

__global__ void init_bar() { g_bar_count = 0u; }

// transpose init [b][k] -> g_h slot 0 [k][b]
__global__ void h0_init(const float* __restrict__ init) {
    int i = blockIdx.x * 256 + threadIdx.x;   // 65536
    int k = i >> 6, b = i & 63;
    g_h[(size_t)k * Bb + b] = init[(size_t)b * Hh + k];
}

// ---------------------------------------------------------------------------
// Phase-3 SGEMM: out[b][t][o] = h[t+1] @ W_out + b_out.
// BM=128 BN=128 BK=16, 256 thr, 8m x 8n tiles. A from g_h [t][k][b] (m=t*64+b).
// ---------------------------------------------------------------------------
__global__ __launch_bounds__(256) void sgemm_out(const float* __restrict__ W,
                                                 const float* __restrict__ bias,
                                                 float* __restrict__ Cout)
{
    __shared__ float As[16][132];
    __shared__ float Bs[16][132];
    const int m0 = blockIdx.y * 128, n0 = blockIdx.x * 128;
    const int tid = threadIdx.x;
    const int tn = tid & 15, tm = tid >> 4;

    u64 acc[8][4];
    #pragma unroll
    for (int m = 0; m < 8; m++)
        #pragma unroll
        for (int p = 0; p < 4; p++) acc[m][p] = 0ull;

    for (int k0 = 0; k0 < Hh; k0 += 16) {
        #pragma unroll
        for (int i = 0; i < 2; i++) {
            int idx = tid + i * 256;            // 2 t-slices x 16 k x 64 b
            int tsl = idx >> 8, k = (idx >> 4) & 15, q = idx & 15;
            float4 v = *(const float4*)(g_h +
                (size_t)((m0 >> 6) + tsl + 1) * (Hh * Bb) + (size_t)(k0 + k) * Bb + q * 4);
            *(float4*)&As[k][tsl * 64 + q * 4] = v;
        }
        #pragma unroll
        for (int i = 0; i < 2; i++) {
            int idx = tid + i * 256;
            int r = idx >> 5, q = idx & 31;
            *(float4*)&Bs[r][q * 4] =
                *(const float4*)(W + (size_t)(k0 + r) * Oo + n0 + q * 4);
        }
        __syncthreads();
        #pragma unroll
        for (int k = 0; k < 16; k++) {
            float4 a0 = *(float4*)&As[k][tm * 8];
            float4 a1 = *(float4*)&As[k][tm * 8 + 4];
            u64 b0 = *(u64*)&Bs[k][tn * 8];
            u64 b1 = *(u64*)&Bs[k][tn * 8 + 2];
            u64 b2 = *(u64*)&Bs[k][tn * 8 + 4];
            u64 b3 = *(u64*)&Bs[k][tn * 8 + 6];
            float av[8] = {a0.x, a0.y, a0.z, a0.w, a1.x, a1.y, a1.z, a1.w};
            #pragma unroll
            for (int m = 0; m < 8; m++) {
                u64 ad = pk2(av[m], av[m]);
                f2(acc[m][0], ad, b0); f2(acc[m][1], ad, b1);
                f2(acc[m][2], ad, b2); f2(acc[m][3], ad, b3);
            }
        }
        __syncthreads();
    }

    const int n = n0 + tn * 8;
    float4 bi0 = *(const float4*)(bias + n);
    float4 bi1 = *(const float4*)(bias + n + 4);
    #pragma unroll
    for (int m = 0; m < 8; m++) {
        int r = m0 + tm * 8 + m;                // r = t*64 + b
        float2 p0 = up2(acc[m][0]), p1 = up2(acc[m][1]);
        float2 p2 = up2(acc[m][2]), p3 = up2(acc[m][3]);
        int t = r >> 6, b = r & 63;
        float* dst = Cout + ((size_t)b * Tt + t) * Oo + n;
        *(float4*)dst = make_float4(p0.x + bi0.x, p0.y + bi0.y, p1.x + bi0.z, p1.y + bi0.w);
        *(float4*)(dst + 4) = make_float4(p2.x + bi1.x, p2.y + bi1.y, p3.x + bi1.z, p3.y + bi1.w);
    }
}

// ---------------------------------------------------------------------------
// Grid barrier: monotonic arrival counter, target = (t+1)*NCTA.
// ---------------------------------------------------------------------------
__device__ __forceinline__ void grid_bar(unsigned t1) {
    __syncthreads();
    if (threadIdx.x == 0) {
        unsigned* pc = &g_bar_count;
        asm volatile("red.add.release.gpu.u32 [%0],1;" :: "l"(pc) : "memory");
        const unsigned target = t1 * NCTA;
        unsigned g;
        do {
            asm volatile("ld.acquire.gpu.u32 %0,[%1];" : "=r"(g) : "l"(pc) : "memory");
        } while (g < target);
    }
    __syncthreads();
}

// ---------------------------------------------------------------------------
// Persistent GRU with FUSED input projection (phase 1 eliminated).
// 128 CTAs x 256 thr. CTA owns 8 hidden units. smem: W_hh slice (96 KB,
// stride 24) + W_ih slice (48 KB, stride 24 + ks-block skew 8) + h double buf.
// Thread = (bq=tid>>4: 4 batches b0=bq*4 | ks=(tid>>2)&3: K/4 | jp=tid&3).
// Main: k = c*128 + kk*4 + ks (interleaved). Fused gi for step t+1:
// k' = ks*128 + c*16 + kg (blocked; X float4-contiguous), X __ldg'd at chunk
// start, FMA'd after the main kk loop. gi result reduced over ks and kept in
// REGISTERS (gcur) on ks==0 lanes — its only consumer is this same thread
// at step t+1's epilogue. Prologue computes gi[0] the same way.
// ---------------------------------------------------------------------------
#define HT_STRIDE 72
#define WS_F (1024 * 24)
#define WI_F (512 * 24 + 32)
#define HT_F (2 * 128 * HT_STRIDE)
#define SMEMB ((WS_F + WI_F + HT_F) * 4)

__global__ __launch_bounds__(256) void gru_persist(const float* __restrict__ X,
                                                   const float* __restrict__ Whh,
                                                   const float* __restrict__ Wih,
                                                   const float* __restrict__ bhh,
                                                   const float* __restrict__ bih)
{
    extern __shared__ float sm[];
    float* Ws = sm;                      // W_hh [k][g*8+u], stride 24
    float* Wi = sm + WS_F;               // W_ih [k'][g*8+u], stride 24 + skew
    float* Ht = sm + WS_F + WI_F;        // [buf2][k][72]

    const int tid = threadIdx.x;
    const int bq = tid >> 4, ks = (tid >> 2) & 3, jp = tid & 3;
    const int b0 = bq * 4;
    const int j0 = blockIdx.x * 8, j = j0 + jp * 2;

    for (int i = tid; i < 1024 * 6; i += 256) {
        int k = i / 6, q = i - k * 6, g = q >> 1, part = q & 1;
        *(float4*)&Ws[k * 24 + g * 8 + part * 4] =
            *(const float4*)(Whh + (size_t)k * Gg + g * Hh + j0 + part * 4);
    }
    for (int i = tid; i < 512 * 6; i += 256) {
        int k = i / 6, q = i - k * 6, g = q >> 1, part = q & 1;
        *(float4*)&Wi[k * 24 + (k >> 7) * 8 + g * 8 + part * 4] =
            *(const float4*)(Wih + (size_t)k * Gg + g * Hh + j0 + part * 4);
    }
    const float2 br = *(const float2*)(bhh + j);
    const float2 bz = *(const float2*)(bhh + Hh + j);
    const float2 bn = *(const float2*)(bhh + 2 * Hh + j);
    const float2 bir = *(const float2*)(bih + j);
    const float2 biz = *(const float2*)(bih + Hh + j);
    const float2 bin = *(const float2*)(bih + 2 * Hh + j);
    __syncthreads();

    // --- fused gi helpers ---
    float4 Xr[4][4];                     // 16 float4: chunk's X for 4 batches
    auto gi_load = [&](int tt, int c) {
        #pragma unroll
        for (int b = 0; b < 4; b++) {
            const float* xp = X + ((size_t)(b0 + b) * Tt + tt) * Ii + ks * 128 + c * 16;
            #pragma unroll
            for (int q = 0; q < 4; q++)
                Xr[b][q] = __ldg((const float4*)(xp + q * 4));
        }
    };
    auto gi_fma = [&](int c, u64 (&a2)[3][4]) {
        const float* wp2 = Wi + (ks * 128 + c * 16) * 24 + ks * 8 + jp * 2;
        #pragma unroll
        for (int kg = 0; kg < 16; kg++) {
            const float* wq = wp2 + kg * 24;
            u64 wr = *(const u64*)wq;
            u64 wz = *(const u64*)(wq + 8);
            u64 wn = *(const u64*)(wq + 16);
            #pragma unroll
            for (int b = 0; b < 4; b++) {
                float xv = ((const float*)&Xr[b][kg >> 2])[kg & 3];
                u64 xd = pk2(xv, xv);
                f2(a2[0][b], xd, wr); f2(a2[1][b], xd, wz); f2(a2[2][b], xd, wn);
            }
        }
    };
    auto reduce2 = [&](u64 (&a2)[3][4]) {
        #pragma unroll
        for (int g = 0; g < 3; g++)
            #pragma unroll
            for (int b = 0; b < 4; b++) {
                u64 v = a2[g][b];
                v = add2(v, __shfl_xor_sync(0xffffffffu, v, 4));
                v = add2(v, __shfl_xor_sync(0xffffffffu, v, 8));
                a2[g][b] = v;
            }
    };

    // --- prologue: gi[0] into registers ---
    float2 gcur[3][4];
    {
        u64 a2[3][4];
        #pragma unroll
        for (int g = 0; g < 3; g++)
            #pragma unroll
            for (int b = 0; b < 4; b++) a2[g][b] = 0ull;
        for (int c = 0; c < 8; ++c) { gi_load(0, c); gi_fma(c, a2); }
        reduce2(a2);
        #pragma unroll
        for (int g = 0; g < 3; g++)
            #pragma unroll
            for (int b = 0; b < 4; b++) gcur[g][b] = up2(a2[g][b]);
    }

    for (int t = 0; t < Tt; ++t) {
        const float* hprev = g_h + (size_t)t * (Hh * Bb);
        float* hout       = g_h + (size_t)(t + 1) * (Hh * Bb);
        const bool fuse = (t + 1 < Tt);

        auto load_chunk = [&](int c, int buf) {
            const float* src = hprev + c * (128 * Bb);
            float* dstb = Ht + buf * (128 * HT_STRIDE);
            #pragma unroll
            for (int i = 0; i < 8; i++) {
                int f4 = i * 256 + tid;            // 2048 f4 = 128 k x 16
                int row = f4 >> 4, q = f4 & 15;
                cp16(dstb + row * HT_STRIDE + q * 4, src + f4 * 4);
            }
            asm volatile("cp.async.commit_group;");
        };
        load_chunk(0, 0);

        float4 hpj, hpj1;
        if (ks == 0) {
            hpj  = *(const float4*)(hprev + (size_t)j * Bb + b0);
            hpj1 = *(const float4*)(hprev + (size_t)(j + 1) * Bb + b0);
        }

        u64 acc[3][4], acc2[3][4];
        #pragma unroll
        for (int g = 0; g < 3; g++)
            #pragma unroll
            for (int b = 0; b < 4; b++) { acc[g][b] = 0ull; acc2[g][b] = 0ull; }

        #pragma unroll 1
        for (int c = 0; c < 8; ++c) {
            if (c < 7) {
                load_chunk(c + 1, (c + 1) & 1);
                asm volatile("cp.async.wait_group 1;");
            } else {
                asm volatile("cp.async.wait_group 0;");
            }
            __syncthreads();
            if (fuse) gi_load(t + 1, c);           // X in flight across kk loop
            const float* hb = Ht + (c & 1) * (128 * HT_STRIDE) + ks * HT_STRIDE + b0;
            const float* wp = Ws + (c * 128 + ks) * 24 + jp * 2;
            #pragma unroll 8
            for (int kk = 0; kk < 32; ++kk) {
                const float* hq = hb + kk * (4 * HT_STRIDE);
                float4 h4 = *(const float4*)hq;
                u64 hd0 = pk2(h4.x, h4.x), hd1 = pk2(h4.y, h4.y);
                u64 hd2 = pk2(h4.z, h4.z), hd3 = pk2(h4.w, h4.w);
                const float* wq = wp + kk * 96;
                u64 wr = *(const u64*)(wq);
                u64 wz = *(const u64*)(wq + 8);
                u64 wn = *(const u64*)(wq + 16);
                f2(acc[0][0], hd0, wr); f2(acc[0][1], hd1, wr);
                f2(acc[0][2], hd2, wr); f2(acc[0][3], hd3, wr);
                f2(acc[1][0], hd0, wz); f2(acc[1][1], hd1, wz);
                f2(acc[1][2], hd2, wz); f2(acc[1][3], hd3, wz);
                f2(acc[2][0], hd0, wn); f2(acc[2][1], hd1, wn);
                f2(acc[2][2], hd2, wn); f2(acc[2][3], hd3, wn);
            }
            if (fuse) gi_fma(c, acc2);
            __syncthreads();
        }

        // reduce main over ks (lane bits 2..3)
        #pragma unroll
        for (int g = 0; g < 3; g++)
            #pragma unroll
            for (int b = 0; b < 4; b++) {
                u64 v = acc[g][b];
                v = add2(v, __shfl_xor_sync(0xffffffffu, v, 4));
                v = add2(v, __shfl_xor_sync(0xffffffffu, v, 8));
                acc[g][b] = v;
            }
        if (fuse) reduce2(acc2);

        if (ks == 0) {
            const float hpv[2][4] = {{hpj.x, hpj.y, hpj.z, hpj.w},
                                     {hpj1.x, hpj1.y, hpj1.z, hpj1.w}};
            float hj[4], hj1[4];
            #pragma unroll
            for (int b = 0; b < 4; b++) {
                float2 sr = up2(acc[0][b]), sz = up2(acc[1][b]), sn = up2(acc[2][b]);
                float r0 = sigm(gcur[0][b].x + bir.x + sr.x + br.x);
                float r1 = sigm(gcur[0][b].y + bir.y + sr.y + br.y);
                float z0 = sigm(gcur[1][b].x + biz.x + sz.x + bz.x);
                float z1 = sigm(gcur[1][b].y + biz.y + sz.y + bz.y);
                float n0 = tanhf(gcur[2][b].x + bin.x + r0 * (sn.x + bn.x));
                float n1 = tanhf(gcur[2][b].y + bin.y + r1 * (sn.y + bn.y));
                hj[b]  = (1.0f - z0) * n0 + z0 * hpv[0][b];
                hj1[b] = (1.0f - z1) * n1 + z1 * hpv[1][b];
            }
            *(float4*)(hout + (size_t)j * Bb + b0) =
                make_float4(hj[0], hj[1], hj[2], hj[3]);
            *(float4*)(hout + (size_t)(j + 1) * Bb + b0) =
                make_float4(hj1[0], hj1[1], hj1[2], hj1[3]);
            if (fuse) {
                #pragma unroll
                for (int g = 0; g < 3; g++)
                    #pragma unroll
                    for (int b = 0; b < 4; b++) gcur[g][b] = up2(acc2[g][b]);
            }
        }
        grid_bar((unsigned)(t + 1));
    }
}

extern "C" void kernel_launch(void* const* d_in, const int* in_sizes, int n_in,
                              void* d_out, int out_size)
{
    const float* X    = (const float*)d_in[0];
    const float* init = (const float*)d_in[1];
    const float* Wih  = (const float*)d_in[2];
    const float* Whh  = (const float*)d_in[3];
    const float* bih  = (const float*)d_in[4];
    const float* bhh  = (const float*)d_in[5];
    const float* Wout = (const float*)d_in[6];
    const float* bout = (const float*)d_in[7];
    float* out = (float*)d_out;

    cudaFuncSetAttribute(gru_persist,
                         cudaFuncAttributeMaxDynamicSharedMemorySize, SMEMB);

    init_bar<<<1, 1>>>();
    h0_init<<<256, 256>>>(init);

    // Phases 1+2 fused: persistent kernel does input projection AND recurrence
    gru_persist<<<NCTA, 256, SMEMB>>>(X, Whh, Wih, bhh, bih);

    // Phase 3: out = h @ W_out + b_out
    sgemm_out<<<dim3(Oo / 128, (Bb * Tt) / 128), 256>>>(Wout, bout, out);
}

// round 17
// speedup vs baseline: 1.0553x; 1.0553x over previous
#include <cuda_runtime.h>
#include <cstdint>

#define Tt 1024
#define Bb 64
#define Ii 512
#define Hh 1024
#define Gg 3072
#define Oo 256
#define NCTA 128
#define NT_TILES 48              // 3072 / 64
#define MT_TILES 512             // 65536 / 128
#define TILES (MT_TILES * NT_TILES)

__device__ float g_gi[(size_t)Tt * Bb * Gg];        // [t][b][g]
__device__ float g_h [(size_t)(Tt + 1) * Hh * Bb];  // [t][k][b], slot 0 = init^T
__device__ unsigned g_flags[MT_TILES];              // ntile completions per mtile
__device__ unsigned g_bar_count;

typedef unsigned long long u64;

__device__ __forceinline__ u64 pk2(float x, float y) {
    u64 r; asm("mov.b64 %0,{%1,%2};" : "=l"(r) : "f"(x), "f"(y)); return r;
}
__device__ __forceinline__ void f2(u64& d, u64 a, u64 b) {
    asm("fma.rn.f32x2 %0,%1,%2,%0;" : "+l"(d) : "l"(a), "l"(b));
}
__device__ __forceinline__ u64 add2(u64 a, u64 b) {
    u64 d; asm("add.rn.f32x2 %0,%1,%2;" : "=l"(d) : "l"(a), "l"(b)); return d;
}
__device__ __forceinline__ float2 up2(u64 a) {
    float2 f; asm("mov.b64 {%0,%1},%2;" : "=f"(f.x), "=f"(f.y) : "l"(a)); return f;
}
__device__ __forceinline__ float sigm(float x) { return 1.0f / (1.0f + __expf(-x)); }
__device__ __forceinline__ void cp16(void* smem, const void* g) {
    uint32_t s = (uint32_t)__cvta_generic_to_shared(smem);
    asm volatile("cp.async.cg.shared.global [%0], [%1], 16;" :: "r"(s), "l"(g));
}
__device__ __forceinline__ void rbar() { asm volatile("bar.sync 1, 256;" ::: "memory"); }
__device__ __forceinline__ void gbar() { asm volatile("bar.sync 2, 256;" ::: "memory"); }

__global__ void reset_state() {
    int i = blockIdx.x * 256 + threadIdx.x;
    if (i < MT_TILES) g_flags[i] = 0u;
    if (i == MT_TILES) g_bar_count = 0u;
}

// transpose init [b][k] -> g_h slot 0 [k][b]
__global__ void h0_init(const float* __restrict__ init) {
    int i = blockIdx.x * 256 + threadIdx.x;   // 65536
    int k = i >> 6, b = i & 63;
    g_h[(size_t)k * Bb + b] = init[(size_t)b * Hh + k];
}

// ---------------------------------------------------------------------------
// Phase-3 SGEMM: out[b][t][o] = h[t+1] @ W_out + b_out (BM128 BN128 BK16).
// ---------------------------------------------------------------------------
__global__ __launch_bounds__(256) void sgemm_out(const float* __restrict__ W,
                                                 const float* __restrict__ bias,
                                                 float* __restrict__ Cout)
{
    __shared__ float As[16][132];
    __shared__ float Bs[16][132];
    const int m0 = blockIdx.y * 128, n0 = blockIdx.x * 128;
    const int tid = threadIdx.x;
    const int tn = tid & 15, tm = tid >> 4;

    u64 acc[8][4];
    #pragma unroll
    for (int m = 0; m < 8; m++)
        #pragma unroll
        for (int p = 0; p < 4; p++) acc[m][p] = 0ull;

    for (int k0 = 0; k0 < Hh; k0 += 16) {
        #pragma unroll
        for (int i = 0; i < 2; i++) {
            int idx = tid + i * 256;
            int tsl = idx >> 8, k = (idx >> 4) & 15, q = idx & 15;
            float4 v = *(const float4*)(g_h +
                (size_t)((m0 >> 6) + tsl + 1) * (Hh * Bb) + (size_t)(k0 + k) * Bb + q * 4);
            *(float4*)&As[k][tsl * 64 + q * 4] = v;
        }
        #pragma unroll
        for (int i = 0; i < 2; i++) {
            int idx = tid + i * 256;
            int r = idx >> 5, q = idx & 31;
            *(float4*)&Bs[r][q * 4] =
                *(const float4*)(W + (size_t)(k0 + r) * Oo + n0 + q * 4);
        }
        __syncthreads();
        #pragma unroll
        for (int k = 0; k < 16; k++) {
            float4 a0 = *(float4*)&As[k][tm * 8];
            float4 a1 = *(float4*)&As[k][tm * 8 + 4];
            u64 b0 = *(u64*)&Bs[k][tn * 8];
            u64 b1 = *(u64*)&Bs[k][tn * 8 + 2];
            u64 b2 = *(u64*)&Bs[k][tn * 8 + 4];
            u64 b3 = *(u64*)&Bs[k][tn * 8 + 6];
            float av[8] = {a0.x, a0.y, a0.z, a0.w, a1.x, a1.y, a1.z, a1.w};
            #pragma unroll
            for (int m = 0; m < 8; m++) {
                u64 ad = pk2(av[m], av[m]);
                f2(acc[m][0], ad, b0); f2(acc[m][1], ad, b1);
                f2(acc[m][2], ad, b2); f2(acc[m][3], ad, b3);
            }
        }
        __syncthreads();
    }

    const int n = n0 + tn * 8;
    float4 bi0 = *(const float4*)(bias + n);
    float4 bi1 = *(const float4*)(bias + n + 4);
    #pragma unroll
    for (int m = 0; m < 8; m++) {
        int r = m0 + tm * 8 + m;
        float2 p0 = up2(acc[m][0]), p1 = up2(acc[m][1]);
        float2 p2 = up2(acc[m][2]), p3 = up2(acc[m][3]);
        int t = r >> 6, b = r & 63;
        float* dst = Cout + ((size_t)b * Tt + t) * Oo + n;
        *(float4*)dst = make_float4(p0.x + bi0.x, p0.y + bi0.y, p1.x + bi0.z, p1.y + bi0.w);
        *(float4*)(dst + 4) = make_float4(p2.x + bi1.x, p2.y + bi1.y, p3.x + bi1.z, p3.y + bi1.w);
    }
}

// ---------------------------------------------------------------------------
// Fused persistent kernel: 128 CTAs x 512 threads.
//   threads 0..255  : GRU recurrence (R6 layout; named barrier 1)
//   threads 256..511: background phase-1 GEMM producing g_gi (named barrier 2)
// smem (floats): Ws 24576 | Ht 18432 | As 2112 | Bs 1088   = 184,832 B
// ---------------------------------------------------------------------------
#define HT_STRIDE 72
#define WS_F (1024 * 24)
#define HT_F (2 * 128 * HT_STRIDE)
#define AS_OFF (WS_F + HT_F)
#define BS_OFF (AS_OFF + 16 * 132)
#define SMEMB ((BS_OFF + 16 * 68) * 4)

__global__ __launch_bounds__(512) void gru_fused(const float* __restrict__ X,
                                                 const float* __restrict__ Whh,
                                                 const float* __restrict__ Wih,
                                                 const float* __restrict__ bih,
                                                 const float* __restrict__ bhh)
{
    extern __shared__ float sm[];
    const int ct = blockIdx.x;

    if (threadIdx.x >= 256) {
        // =================== producer half: phase-1 GEMM ===================
        const int tid = threadIdx.x - 256;
        float (*As)[132] = (float(*)[132])(sm + AS_OFF);
        float (*Bs)[68]  = (float(*)[68])(sm + BS_OFF);
        const int tn = tid & 15, tm = tid >> 4;

        for (int g = ct; g < TILES; g += NCTA) {
            const int mt = g / NT_TILES, nt = g - mt * NT_TILES;
            const int m0 = mt * 128, n0 = nt * 64;

            u64 acc[8][2];
            #pragma unroll
            for (int m = 0; m < 8; m++) { acc[m][0] = 0ull; acc[m][1] = 0ull; }

            for (int k0 = 0; k0 < Ii; k0 += 16) {
                #pragma unroll
                for (int i = 0; i < 2; i++) {
                    int idx = tid + i * 256;       // 512 f4 = 128 rows x 4
                    int r = idx >> 2, kq = idx & 3;
                    int m = m0 + r;                // m = t*64 + b
                    float4 v = *(const float4*)(X +
                        ((size_t)(m & 63) * Tt + (m >> 6)) * Ii + k0 + kq * 4);
                    As[kq * 4 + 0][r] = v.x; As[kq * 4 + 1][r] = v.y;
                    As[kq * 4 + 2][r] = v.z; As[kq * 4 + 3][r] = v.w;
                }
                {
                    int r = tid >> 4, gq = tid & 15;   // 16 k x 16 f4
                    *(float4*)&Bs[r][gq * 4] =
                        *(const float4*)(Wih + (size_t)(k0 + r) * Gg + n0 + gq * 4);
                }
                gbar();
                #pragma unroll
                for (int k = 0; k < 16; k++) {
                    float4 a0 = *(float4*)&As[k][tm * 8];
                    float4 a1 = *(float4*)&As[k][tm * 8 + 4];
                    u64 b0 = *(u64*)&Bs[k][tn * 4];
                    u64 b1 = *(u64*)&Bs[k][tn * 4 + 2];
                    float av[8] = {a0.x, a0.y, a0.z, a0.w, a1.x, a1.y, a1.z, a1.w};
                    #pragma unroll
                    for (int m = 0; m < 8; m++) {
                        u64 ad = pk2(av[m], av[m]);
                        f2(acc[m][0], ad, b0);
                        f2(acc[m][1], ad, b1);
                    }
                }
                gbar();
            }

            const int n = n0 + tn * 4;
            float4 bi = *(const float4*)(bih + n);
            #pragma unroll
            for (int m = 0; m < 8; m++) {
                int r = m0 + tm * 8 + m;           // r = t*64 + b
                float2 p0 = up2(acc[m][0]), p1 = up2(acc[m][1]);
                int t = r >> 6, b = r & 63;
                *(float4*)(g_gi + ((size_t)t * Bb + b) * Gg + n) =
                    make_float4(p0.x + bi.x, p0.y + bi.y, p1.x + bi.z, p1.y + bi.w);
            }
            __threadfence();
            gbar();
            if (tid == 0)
                asm volatile("red.add.release.gpu.u32 [%0],1;"
                             :: "l"(&g_flags[mt]) : "memory");
        }
        return;
    }

    // ===================== consumer half: GRU recurrence =====================
    const int tid = threadIdx.x;
    float* Ws = sm;
    float* Ht = sm + WS_F;
    const int bq = tid >> 4, ks = (tid >> 2) & 3, jp = tid & 3;
    const int b0 = bq * 4;
    const int j0 = ct * 8, j = j0 + jp * 2;

    for (int i = tid; i < 1024 * 6; i += 256) {
        int k = i / 6, q = i - k * 6, g = q >> 1, part = q & 1;
        *(float4*)&Ws[k * 24 + g * 8 + part * 4] =
            *(const float4*)(Whh + (size_t)k * Gg + g * Hh + j0 + part * 4);
    }
    const float2 br = *(const float2*)(bhh + j);
    const float2 bz = *(const float2*)(bhh + Hh + j);
    const float2 bn = *(const float2*)(bhh + 2 * Hh + j);
    rbar();

    for (int t = 0; t < Tt; ++t) {
        const float* hprev = g_h + (size_t)t * (Hh * Bb);
        float* hout       = g_h + (size_t)(t + 1) * (Hh * Bb);

        auto load_chunk = [&](int c, int buf) {
            const float* src = hprev + c * (128 * Bb);
            float* dstb = Ht + buf * (128 * HT_STRIDE);
            #pragma unroll
            for (int i = 0; i < 8; i++) {
                int f4 = i * 256 + tid;
                int row = f4 >> 4, q = f4 & 15;
                cp16(dstb + row * HT_STRIDE + q * 4, src + f4 * 4);
            }
            asm volatile("cp.async.commit_group;");
        };
        load_chunk(0, 0);

        float4 hpj, hpj1;
        if (ks == 0) {
            hpj  = *(const float4*)(hprev + (size_t)j * Bb + b0);
            hpj1 = *(const float4*)(hprev + (size_t)(j + 1) * Bb + b0);
        }

        u64 acc[3][4];
        #pragma unroll
        for (int g = 0; g < 3; g++)
            #pragma unroll
            for (int b = 0; b < 4; b++) acc[g][b] = 0ull;

        #pragma unroll 1
        for (int c = 0; c < 8; ++c) {
            if (c < 7) {
                load_chunk(c + 1, (c + 1) & 1);
                asm volatile("cp.async.wait_group 1;");
            } else {
                asm volatile("cp.async.wait_group 0;");
            }
            rbar();
            const float* hb = Ht + (c & 1) * (128 * HT_STRIDE) + ks * HT_STRIDE + b0;
            const float* wp = Ws + (c * 128 + ks) * 24 + jp * 2;
            #pragma unroll 8
            for (int kk = 0; kk < 32; ++kk) {
                const float* hq = hb + kk * (4 * HT_STRIDE);
                float4 h4 = *(const float4*)hq;
                u64 hd0 = pk2(h4.x, h4.x), hd1 = pk2(h4.y, h4.y);
                u64 hd2 = pk2(h4.z, h4.z), hd3 = pk2(h4.w, h4.w);
                const float* wq = wp + kk * 96;
                u64 wr = *(const u64*)(wq);
                u64 wz = *(const u64*)(wq + 8);
                u64 wn = *(const u64*)(wq + 16);
                f2(acc[0][0], hd0, wr); f2(acc[0][1], hd1, wr);
                f2(acc[0][2], hd2, wr); f2(acc[0][3], hd3, wr);
                f2(acc[1][0], hd0, wz); f2(acc[1][1], hd1, wz);
                f2(acc[1][2], hd2, wz); f2(acc[1][3], hd3, wz);
                f2(acc[2][0], hd0, wn); f2(acc[2][1], hd1, wn);
                f2(acc[2][2], hd2, wn); f2(acc[2][3], hd3, wn);
            }
            rbar();
        }

        // gate on gi[t] ready (flags[t>>1] == NT_TILES), one poll lane/warp
        {
            const unsigned* f = &g_flags[t >> 1];
            unsigned v;
            do {
                if ((tid & 31) == 0)
                    asm volatile("ld.acquire.gpu.u32 %0,[%1];" : "=r"(v) : "l"(f) : "memory");
                v = __shfl_sync(0xffffffffu, v, 0);
            } while (v < NT_TILES);
        }

        // gi loads (now safe) overlap the shfl reduction
        float2 gir[4], giz[4], gin[4];
        if (ks == 0) {
            const float* gp = g_gi + ((size_t)t * Bb + b0) * Gg;
            #pragma unroll
            for (int b = 0; b < 4; b++) {
                gir[b] = *(const float2*)(gp + (size_t)b * Gg + j);
                giz[b] = *(const float2*)(gp + (size_t)b * Gg + Hh + j);
                gin[b] = *(const float2*)(gp + (size_t)b * Gg + 2 * Hh + j);
            }
        }

        #pragma unroll
        for (int g = 0; g < 3; g++)
            #pragma unroll
            for (int b = 0; b < 4; b++) {
                u64 v = acc[g][b];
                v = add2(v, __shfl_xor_sync(0xffffffffu, v, 4));
                v = add2(v, __shfl_xor_sync(0xffffffffu, v, 8));
                acc[g][b] = v;
            }

        if (ks == 0) {
            const float hpv[2][4] = {{hpj.x, hpj.y, hpj.z, hpj.w},
                                     {hpj1.x, hpj1.y, hpj1.z, hpj1.w}};
            float hj[4], hj1[4];
            #pragma unroll
            for (int b = 0; b < 4; b++) {
                float2 sr = up2(acc[0][b]), sz = up2(acc[1][b]), sn = up2(acc[2][b]);
                float r0 = sigm(gir[b].x + sr.x + br.x);
                float r1 = sigm(gir[b].y + sr.y + br.y);
                float z0 = sigm(giz[b].x + sz.x + bz.x);
                float z1 = sigm(giz[b].y + sz.y + bz.y);
                float n0 = tanhf(gin[b].x + r0 * (sn.x + bn.x));
                float n1 = tanhf(gin[b].y + r1 * (sn.y + bn.y));
                hj[b]  = (1.0f - z0) * n0 + z0 * hpv[0][b];
                hj1[b] = (1.0f - z1) * n1 + z1 * hpv[1][b];
            }
            *(float4*)(hout + (size_t)j * Bb + b0) =
                make_float4(hj[0], hj[1], hj[2], hj[3]);
            *(float4*)(hout + (size_t)(j + 1) * Bb + b0) =
                make_float4(hj1[0], hj1[1], hj1[2], hj1[3]);
        }

        // grid barrier over the 128 recurrence halves
        rbar();
        if (tid == 0) {
            asm volatile("red.add.release.gpu.u32 [%0],1;" :: "l"(&g_bar_count) : "memory");
            const unsigned target = (unsigned)(t + 1) * NCTA;
            unsigned g;
            do {
                asm volatile("ld.acquire.gpu.u32 %0,[%1];" : "=r"(g) : "l"(&g_bar_count) : "memory");
            } while (g < target);
        }
        rbar();
    }
}

extern "C" void kernel_launch(void* const* d_in, const int* in_sizes, int n_in,
                              void* d_out, int out_size)
{
    const float* X    = (const float*)d_in[0];
    const float* init = (const float*)d_in[1];
    const float* Wih  = (const float*)d_in[2];
    const float* Whh  = (const float*)d_in[3];
    const float* bih  = (const float*)d_in[4];
    const float* bhh  = (const float*)d_in[5];
    const float* Wout = (const float*)d_in[6];
    const float* bout = (const float*)d_in[7];
    float* out = (float*)d_out;

    cudaFuncSetAttribute(gru_fused,
                         cudaFuncAttributeMaxDynamicSharedMemorySize, SMEMB);

    reset_state<<<3, 256>>>();
    h0_init<<<256, 256>>>(init);

    // Phases 1+2: warp-specialized persistent kernel (gi produced concurrently)
    gru_fused<<<NCTA, 512, SMEMB>>>(X, Whh, Wih, bih, bhh);

    // Phase 3: out = h @ W_out + b_out
    sgemm_out<<<dim3(Oo / 128, (Bb * Tt) / 128), 256>>>(Wout, bout, out);
}